// round 17
// baseline (speedup 1.0000x reference)
#include <cuda_runtime.h>
#include <cuda_bf16.h>
#include <cuda_fp16.h>
#include <cstdint>

// ---------------- problem dims ----------------
#define BATCH 64
#define SEQ   512
#define ISZ   512
#define HSZ   1024
#define GSZ   4096
#define NCTA  128            // 2 batch-groups x 64 column-groups
#define NCG   64             // column groups
#define UPC   16             // hidden units per cg (64 gate cols)
#define MB    32             // batches per CTA
#define WORDS_H (64 * 4 * 32 * 4)      // 32768 u32 per cg (paired fp16 frags)
#define WORDS_X (32 * 8 * 32 * 2)      // 16384 u32 per cg (K=512, N=64)
#define CBQ   2              // cg blocks per xw CTA
#define NKTX  16             // k32 tiles in x GEMM

// recurrent smem layout (bytes): W 128KB, then 2 A stages (32 rows x k512)
#define SM_A     131072
#define A_STRIDE 1040                   // 1024B data + 16B pad
#define A_STG    (32 * A_STRIDE)        // 33280 per stage
#define SMEM_TOTAL (SM_A + 2 * A_STG)   // 197632
// gate-partial overlay on A stage 0: [32][65][4] floats = 33280 B exactly
// addr(r,c,kw) = ((r*65 + c)*4 + kw) floats  -> float4 readable per (r,c)

// xw smem (dynamic): 3 stages A + 3 stages B
#define XG_A_STAGE 10240     // 128 rows x 80B (fp16 k32)
#define XG_B_STAGE 8192      // 2 cg x 4KB
#define XG_SMEM (3 * (XG_A_STAGE + XG_B_STAGE))   // 55296

// ---------------- persistent device scratch ----------------
__device__ __align__(256) unsigned g_Whf[(size_t)NCG * WORDS_H];      // 8 MB
__device__ __align__(256) unsigned g_Wxf[(size_t)NCG * WORDS_X];      // 4 MB
__device__ __align__(256) __half   g_xh[(size_t)BATCH * SEQ * ISZ];   // 32 MB
__device__ __align__(256) __half   g_xg[(size_t)SEQ * NCG * BATCH * 64]; // 256 MB
__device__ __align__(256) __half   g_h[2][BATCH * HSZ];               // fp16 h, ping-pong
__device__ __align__(128) unsigned g_flags[NCTA * 32];

// ---------------- helpers ----------------
__device__ __forceinline__ void cp_async16_s(uint32_t dst_smem, const void* src) {
    asm volatile("cp.async.cg.shared.global [%0], [%1], 16;\n"
                 :: "r"(dst_smem), "l"(src) : "memory");
}
__device__ __forceinline__ void cp_commit() {
    asm volatile("cp.async.commit_group;\n" ::: "memory");
}
// cancellation-safe fast activations (abs err <= ~3e-7)
__device__ __forceinline__ float fsig(float v) {
    return __fdividef(1.0f, 1.0f + __expf(-v));
}
__device__ __forceinline__ float ftanh2(float v) {
    v = fminf(fmaxf(v, -30.0f), 30.0f);
    float u = __expf(-2.0f * v);
    return __fdividef(1.0f - u, 1.0f + u);
}

#define LDSM4(R, ADDR) \
    asm volatile("ldmatrix.sync.aligned.m8n8.x4.shared.b16 {%0,%1,%2,%3},[%4];" \
                 : "=r"((R)[0]), "=r"((R)[1]), "=r"((R)[2]), "=r"((R)[3]) : "r"(ADDR))

#define MMA_F16(ACC, A, B0, B1) \
    asm volatile("mma.sync.aligned.m16n8k16.row.col.f32.f16.f16.f32 " \
                 "{%0,%1,%2,%3},{%4,%5,%6,%7},{%8,%9},{%0,%1,%2,%3};" \
                 : "+f"((ACC)[0]), "+f"((ACC)[1]), "+f"((ACC)[2]), "+f"((ACC)[3]) \
                 : "r"((A)[0]), "r"((A)[1]), "r"((A)[2]), "r"((A)[3]), "r"(B0), "r"(B1))

#define LDSV2(R0, R1, ADDR) \
    asm volatile("ld.shared.v2.u32 {%0,%1},[%2];" : "=r"(R0), "=r"(R1) : "r"(ADDR))

#define LDSV4(R0, R1, R2, R3, ADDR) \
    asm volatile("ld.shared.v4.u32 {%0,%1,%2,%3},[%4];" \
                 : "=r"(R0), "=r"(R1), "=r"(R2), "=r"(R3) : "r"(ADDR))

// ---------------- prep kernels ----------------
__global__ void prep_x(const float* __restrict__ x) {
    size_t i = (size_t)blockIdx.x * blockDim.x + threadIdx.x;
    size_t n4 = (size_t)BATCH * SEQ * ISZ / 4;
    if (i >= n4) return;
    float4 v = reinterpret_cast<const float4*>(x)[i];
    __half2* d = reinterpret_cast<__half2*>(g_xh);
    d[i * 2]     = __halves2half2(__float2half_rn(v.x), __float2half_rn(v.y));
    d[i * 2 + 1] = __halves2half2(__float2half_rn(v.z), __float2half_rn(v.w));
}

// Wh fragments fp16 (K=1024, N=64 per cg), PAIRED layout:
// word w = ((((cg*64 + k16)*4 + np)*32 + lane)*4 + n8lo*2 + q
// -> byte addr (cg-local) = (k16*4 + np)*512 + lane*16 + n8lo*8 + q*4.
// One LDS.128 per (k16, np) yields both n8 = 2np and 2np+1 fragments.
__global__ void prep_wh(const float* __restrict__ W) {
    size_t w = (size_t)blockIdx.x * blockDim.x + threadIdx.x;
    if (w >= (size_t)NCG * WORDS_H) return;
    int q    = (int)(w & 1);
    int n8lo = (int)((w >> 1) & 1);
    int lane = (int)((w >> 2) & 31);
    int np   = (int)((w >> 7) & 3);
    int k16  = (int)((w >> 9) & 63);
    int cg   = (int)(w >> 15);
    int n8 = np * 2 + n8lo;
    int k  = k16 * 16 + (lane & 3) * 2 + q * 8;
    int nl = n8 * 8 + (lane >> 2);
    int col = (nl >> 4) * HSZ + cg * UPC + (nl & 15);
    __half h0 = __float2half_rn(W[(size_t)(ISZ + k) * GSZ + col]);
    __half h1 = __float2half_rn(W[(size_t)(ISZ + k + 1) * GSZ + col]);
    __half2 ph = __halves2half2(h0, h1);
    g_Whf[w] = *reinterpret_cast<unsigned*>(&ph);
}

// Wx fragments fp16 (K=512, N=64 per cg) — unchanged layout.
__global__ void prep_wx(const float* __restrict__ W) {
    size_t w = (size_t)blockIdx.x * blockDim.x + threadIdx.x;
    if (w >= (size_t)NCG * WORDS_X) return;
    int q    = (int)(w & 1);
    int lane = (int)((w >> 1) & 31);
    int n8   = (int)((w >> 6) & 7);
    int k16  = (int)((w >> 9) & 31);
    int cg   = (int)(w >> 14);
    int k  = k16 * 16 + (lane & 3) * 2 + q * 8;
    int nl = n8 * 8 + (lane >> 2);
    int col = (nl >> 4) * HSZ + cg * UPC + (nl & 15);
    __half h0 = __float2half_rn(W[(size_t)k * GSZ + col]);
    __half h1 = __float2half_rn(W[(size_t)(k + 1) * GSZ + col]);
    __half2 ph = __halves2half2(h0, h1);
    g_Wxf[w] = *reinterpret_cast<unsigned*>(&ph);
}

__global__ void prep_state() {
    int i = blockIdx.x * blockDim.x + threadIdx.x;
    if (i < 2 * BATCH * HSZ) (&g_h[0][0])[i] = __float2half(0.0f);
    if (i < NCTA * 32) g_flags[i] = 0u;
}

// ---------------- xg precompute GEMM (fp16, K=512) — unchanged ------------
__global__ void __launch_bounds__(256) xw_gemm(const float* __restrict__ bias) {
    extern __shared__ char smem[];
    const uint32_t sA_u = (uint32_t)__cvta_generic_to_shared(smem);
    const uint32_t sB_u = sA_u + 3 * XG_A_STAGE;

    const int tid  = threadIdx.x;
    const int warp = tid >> 5;
    const int lane = tid & 31;
    const int bx   = blockIdx.x;
    const int cg0  = blockIdx.y * CBQ;
    const int mw   = warp >> 1;
    const int nw   = warp & 1;

    float acc[2][8][4];
#pragma unroll
    for (int a = 0; a < 2; a++)
#pragma unroll
        for (int b = 0; b < 8; b++)
#pragma unroll
            for (int c = 0; c < 4; c++) acc[a][b][c] = 0.0f;

    auto load_tile = [&](int kt, int stage) {
        const int k0 = kt * 32;
#pragma unroll
        for (int j = 0; j < 2; j++) {
            int ch = tid + j * 256;
            int rr = ch >> 2, cc = ch & 3;
            cp_async16_s(sA_u + stage * XG_A_STAGE + rr * 80 + cc * 16,
                         g_xh + ((size_t)(bx * 128 + rr)) * ISZ + k0 + cc * 8);
        }
#pragma unroll
        for (int j = 0; j < 2; j++) {
            int ch = tid + j * 256;
            int q = ch >> 8, ww = ch & 255;
            const unsigned* src = g_Wxf + (size_t)(cg0 + q) * WORDS_X + kt * 1024 + ww * 4;
            cp_async16_s(sB_u + stage * XG_B_STAGE + q * 4096 + ww * 16, src);
        }
        cp_commit();
    };

    load_tile(0, 0);
    load_tile(1, 1);

    const uint32_t arow = (uint32_t)((mw * 32 + (lane & 15)) * 80 + (lane >> 4) * 16);

#pragma unroll
    for (int kt = 0; kt < NKTX; kt++) {
        if (kt == NKTX - 1) { asm volatile("cp.async.wait_group 0;\n" ::: "memory"); }
        else                { asm volatile("cp.async.wait_group 1;\n" ::: "memory"); }
        __syncthreads();
        if (kt + 2 < NKTX) load_tile(kt + 2, (kt + 2) % 3);

        const int stage = kt % 3;
        const uint32_t Ab = sA_u + stage * XG_A_STAGE + arow;
        const uint32_t Bb = sB_u + stage * XG_B_STAGE + nw * 4096 + lane * 8;
#pragma unroll
        for (int sub = 0; sub < 2; sub++) {
            uint32_t a0[4], a1[4];
            LDSM4(a0, Ab + sub * 32);
            LDSM4(a1, Ab + 16 * 80 + sub * 32);
#pragma unroll
            for (int ni = 0; ni < 8; ni++) {
                uint32_t b0, b1;
                LDSV2(b0, b1, Bb + (sub * 8 + ni) * 256);
                MMA_F16(acc[0][ni], a0, b0, b1);
                MMA_F16(acc[1][ni], a1, b0, b1);
            }
        }
    }

    const int g = lane >> 2, t4 = lane & 3;
    const int cg = cg0 + nw;
#pragma unroll
    for (int ni = 0; ni < 8; ni++) {
        const int gc0 = ni * 8 + t4 * 2;          // local col = gate*16+ui
        const int gate = gc0 >> 4, ui = gc0 & 15;
        const float bv0 = bias[gate * HSZ + cg * UPC + ui];
        const float bv1 = bias[gate * HSZ + cg * UPC + ui + 1];
#pragma unroll
        for (int mi = 0; mi < 2; mi++) {
#pragma unroll
            for (int rr = 0; rr < 2; rr++) {
                const int r = mw * 32 + mi * 16 + rr * 8 + g;
                const int m = bx * 128 + r;
                const int b = m >> 9, t = m & 511;
                __half2 pv = __halves2half2(
                    __float2half_rn(acc[mi][ni][rr * 2]     + bv0),
                    __float2half_rn(acc[mi][ni][rr * 2 + 1] + bv1));
                __half2* dst = reinterpret_cast<__half2*>(
                    g_xg + (((size_t)t * NCG + cg) * BATCH + b) * 64 + gc0);
                *dst = pv;
            }
        }
    }
}

// ---------------- persistent recurrent kernel ----------------
// 128 CTAs x 256 threads (8 warps = 4K x 2N). R16 skeleton; changes:
// paired-B LDS.128 fetch, float4 partial planes.
__global__ void __launch_bounds__(256, 1) lstm_persist(
    float* __restrict__ out, int write_final)
{
    extern __shared__ char smem[];
    float*  sGf = reinterpret_cast<float*>(smem + SM_A);   // [32][65][4] overlay
    const float4* sGv = reinterpret_cast<const float4*>(smem + SM_A);

    const int tid  = threadIdx.x;
    const int warp = tid >> 5;
    const int lane = tid & 31;
    const int cb   = blockIdx.x;
    const int cg   = cb & 63;
    const int bg   = cb >> 6;
    const int kw   = warp & 3;           // K slice (k128 per stage)
    const int nw   = warp >> 2;          // N half (n32)

    // resident W fragment preload (once): 128KB
    {
        const uint4* sh = reinterpret_cast<const uint4*>(g_Whf + (size_t)cg * WORDS_H);
        uint4* dh = reinterpret_cast<uint4*>(smem);
        for (int i = tid; i < WORDS_H / 4; i += 256) dh[i] = sh[i];
    }

    float cst0 = 0.0f, cst1 = 0.0f;

    const uint32_t sW_u = (uint32_t)__cvta_generic_to_shared(smem);
    const uint32_t sA_u = sW_u + SM_A;
    const uint32_t abase = (uint32_t)((lane & 15) * A_STRIDE + kw * 256 + (lane >> 4) * 16);
    const int l_row = tid >> 3;          // 0..31
    const int l_cc  = tid & 7;           // 0..7

    // collective spin: thread tid<64 verifies flag of same-bg CTA (bg,tid)
    const unsigned* myspin = (const unsigned*)(g_flags + (bg * NCG + (tid & 63)) * 32);
    unsigned* myflag = g_flags + cb * 32;

    __syncthreads();

    for (int t = 0; t < SEQ; t++) {
        const int rb = t & 1, wb = rb ^ 1;
        float acc[2][4][4];
#pragma unroll
        for (int a = 0; a < 2; a++)
#pragma unroll
            for (int b = 0; b < 4; b++)
#pragma unroll
                for (int c = 0; c < 4; c++) acc[a][b][c] = 0.0f;

        // xg prefetch (flag-independent): overlaps the spin wait
        float xg[2][4];
#pragma unroll
        for (int pp = 0; pp < 2; pp++) {
            const int p  = tid + pp * 256;
            const int bl = p >> 4, ui = p & 15;
            const __half* xgp = g_xg +
                (((size_t)t * NCG + cg) * BATCH + bg * MB + bl) * 64;
            xg[pp][0] = __half2float(xgp[ui]);
            xg[pp][1] = __half2float(xgp[16 + ui]);
            xg[pp][2] = __half2float(xgp[32 + ui]);
            xg[pp][3] = __half2float(xgp[48 + ui]);
        }

        // COLLECTIVE barrier (R12/R16-proven): 64 threads cover all 64
        // same-bg flags, then a CTA sync gates every load below.
        if (tid < NCG) {
            const unsigned tgt = 8u * (unsigned)t;
            unsigned v;
            do {
                asm volatile("ld.acquire.gpu.u32 %0, [%1];" : "=r"(v) : "l"(myspin) : "memory");
            } while (v < tgt);
        }
        __syncthreads();

        // both A stages issued up-front (stage-1 latency overlaps stage-0's)
        {
            const __half* src0 = g_h[rb] + (size_t)(bg * MB + l_row) * HSZ + l_cc * 8;
            const uint32_t dst0 = sA_u + l_row * A_STRIDE + l_cc * 16;
#pragma unroll
            for (int j = 0; j < 8; j++)
                cp_async16_s(dst0 + j * 128, src0 + j * 64);
            cp_commit();
#pragma unroll
            for (int j = 0; j < 8; j++)
                cp_async16_s(dst0 + A_STG + j * 128, src0 + 512 + j * 64);
            cp_commit();
        }

#pragma unroll
        for (int s = 0; s < 2; s++) {
            if (s == 0) { asm volatile("cp.async.wait_group 1;\n" ::: "memory"); }
            else        { asm volatile("cp.async.wait_group 0;\n" ::: "memory"); }
            __syncthreads();

            const uint32_t Ab = sA_u + s * A_STG + abase;
#pragma unroll
            for (int j = 0; j < 8; j++) {
                uint32_t a0[4], a1[4];
                LDSM4(a0, Ab + j * 32);
                LDSM4(a1, Ab + 16 * A_STRIDE + j * 32);
                const int k16g = s * 32 + kw * 8 + j;
#pragma unroll
                for (int ni2 = 0; ni2 < 2; ni2++) {
                    const int np = nw * 2 + ni2;
                    const uint32_t Bb = sW_u
                        + (uint32_t)((k16g * 4 + np) * 512 + lane * 16);
                    uint32_t b0, b1, b2, b3;
                    LDSV4(b0, b1, b2, b3, Bb);
                    MMA_F16(acc[0][ni2 * 2],     a0, b0, b1);
                    MMA_F16(acc[1][ni2 * 2],     a1, b0, b1);
                    MMA_F16(acc[0][ni2 * 2 + 1], a0, b2, b3);
                    MMA_F16(acc[1][ni2 * 2 + 1], a1, b2, b3);
                }
            }
        }

        // K-partial store, transposed planes: float index ((r*65 + c)*4 + kw)
        // (overlay on A stage 0; safe: all warps passed the s=1 sync)
        {
            const int g = lane >> 2, t4 = lane & 3;
#pragma unroll
            for (int mi = 0; mi < 2; mi++)
#pragma unroll
                for (int ni = 0; ni < 4; ni++) {
                    const int r = mi * 16 + g;
                    const int c = (nw * 4 + ni) * 8 + t4 * 2;
                    const int i0 = (r * 65 + c) * 4 + kw;
                    sGf[i0]     = acc[mi][ni][0];
                    sGf[i0 + 4] = acc[mi][ni][1];
                    const int i1 = ((r + 8) * 65 + c) * 4 + kw;
                    sGf[i1]     = acc[mi][ni][2];
                    sGf[i1 + 4] = acc[mi][ni][3];
                }
        }
        __syncthreads();

        // reduce 4 K-partials (float4 per gate) + cell update
        float hval[2];
        int   bidx[2], uidx[2];
#pragma unroll
        for (int pp = 0; pp < 2; pp++) {
            const int p  = tid + pp * 256;
            const int bl = p >> 4, ui = p & 15;
            float4 vf = sGv[bl * 65 + ui];
            float4 vi = sGv[bl * 65 + 16 + ui];
            float4 vc = sGv[bl * 65 + 32 + ui];
            float4 vo = sGv[bl * 65 + 48 + ui];
            float gf  = ((vf.x + vf.y) + vf.z) + vf.w;
            float gi  = ((vi.x + vi.y) + vi.z) + vi.w;
            float gc_ = ((vc.x + vc.y) + vc.z) + vc.w;
            float go  = ((vo.x + vo.y) + vo.z) + vo.w;
            float fg = fsig(gf  + xg[pp][0]);
            float ig = fsig(gi  + xg[pp][1]);
            float cg2 = ftanh2(gc_ + xg[pp][2]);
            float og = fsig(go  + xg[pp][3]);
            float& cst = pp ? cst1 : cst0;
            cst = fg * cst + ig * cg2;
            float h = og * ftanh2(cst);
            const int b = bg * MB + bl;
            const int u = cg * UPC + ui;
            g_h[wb][b * HSZ + u] = __float2half_rn(h);
            hval[pp] = h; bidx[pp] = b; uidx[pp] = u;
        }

        // per-warp release (R16-proven): __syncwarp orders the warp's
        // h-stores, one release-add per warp; consumers need 8 arrivals.
        __syncwarp();
        if (lane == 0) {
            asm volatile("red.release.gpu.global.add.u32 [%0], %1;"
                         :: "l"(myflag), "r"(1u) : "memory");
        }

        // non-critical output stores overlap other CTAs' progress
#pragma unroll
        for (int pp = 0; pp < 2; pp++) {
            out[((size_t)bidx[pp] * SEQ + t) * HSZ + uidx[pp]] = hval[pp];
            if (t == SEQ - 1 && write_final) {
                out[(size_t)BATCH * SEQ * HSZ + bidx[pp] * HSZ + uidx[pp]] = hval[pp];
                out[(size_t)BATCH * SEQ * HSZ + BATCH * HSZ + bidx[pp] * HSZ + uidx[pp]]
                    = pp ? cst1 : cst0;
            }
        }
    }
}

// ---------------- launch ----------------
extern "C" void kernel_launch(void* const* d_in, const int* in_sizes, int n_in,
                              void* d_out, int out_size) {
    const float* x = nullptr;
    const float* W = nullptr;
    const float* bias = nullptr;
    for (int i = 0; i < n_in; i++) {
        if (in_sizes[i] == BATCH * SEQ * ISZ)           x = (const float*)d_in[i];
        else if (in_sizes[i] == (ISZ + HSZ) * GSZ)      W = (const float*)d_in[i];
        else if (in_sizes[i] == GSZ)                    bias = (const float*)d_in[i];
    }
    float* out = (float*)d_out;
    const long long full = (long long)BATCH * SEQ * HSZ + 2LL * BATCH * HSZ;
    const int write_final = (out_size >= full) ? 1 : 0;

    cudaFuncSetAttribute(lstm_persist, cudaFuncAttributeMaxDynamicSharedMemorySize, SMEM_TOTAL);
    cudaFuncSetAttribute(xw_gemm, cudaFuncAttributeMaxDynamicSharedMemorySize, XG_SMEM);

    {
        int n4 = BATCH * SEQ * ISZ / 4;
        prep_x<<<(n4 + 255) / 256, 256>>>(x);
    }
    {
        long long n = (long long)NCG * WORDS_H;
        prep_wh<<<(unsigned)((n + 255) / 256), 256>>>(W);
    }
    {
        long long n = (long long)NCG * WORDS_X;
        prep_wx<<<(unsigned)((n + 255) / 256), 256>>>(W);
    }
    prep_state<<<(2 * BATCH * HSZ + 255) / 256, 256>>>();

    {
        dim3 grid(SEQ * BATCH / 128, NCG / CBQ);
        xw_gemm<<<grid, 256, XG_SMEM>>>(bias);
    }

    lstm_persist<<<NCTA, 256, SMEM_TOTAL>>>(out, write_final);
}